// round 4
// baseline (speedup 1.0000x reference)
#include <cuda_runtime.h>
#include <math.h>

#define N_POINTS   4194304
#define NUM_LEVELS 16
#define HASH_MASK  ((1u << 19) - 1u)
#define BLOCK      256
#define ROW_PAD    34   // 32 feats + 2 pad floats: 8B-aligned rows, 2-way LDS/STS conflict = crossbar floor

struct ResParams { float rm1[NUM_LEVELS]; };

#define L1_CUTOFF 6     // levels >= 6 have multi-MB tables: bypass L1 (.cg)

__global__ __launch_bounds__(BLOCK)
void hashenc_kernel(const float*  __restrict__ pts,
                    const float*  __restrict__ tables,
                    float*        __restrict__ out,
                    ResParams rp)
{
    __shared__ float sm[BLOCK * ROW_PAD];

    const int t = threadIdx.x;
    const int n = blockIdx.x * BLOCK + t;

    const float x = __ldcs(pts + 3 * (size_t)n + 0);
    const float y = __ldcs(pts + 3 * (size_t)n + 1);
    const float z = __ldcs(pts + 3 * (size_t)n + 2);

    // normalize [-1,1] -> [0,1], clamp (matches jnp.clip((p+1)*0.5, 0, 1))
    const float fx = fminf(fmaxf((x + 1.0f) * 0.5f, 0.0f), 1.0f);
    const float fy = fminf(fmaxf((y + 1.0f) * 0.5f, 0.0f), 1.0f);
    const float fz = fminf(fmaxf((z + 1.0f) * 0.5f, 0.0f), 1.0f);

    // Phase 1: all 16 hash indices (pure ALU).
    unsigned h[NUM_LEVELS];
    #pragma unroll
    for (int l = 0; l < NUM_LEVELS; ++l) {
        const float rm1 = rp.rm1[l];
        const unsigned cx = (unsigned)(fx * rm1);   // trunc == floor (non-negative)
        const unsigned cy = (unsigned)(fy * rm1);
        const unsigned cz = (unsigned)(fz * rm1);
        h[l] = (cx ^ (cy * 2654435761u) ^ (cz * 805459861u)) & HASH_MASK;
    }

    // Phase 2: 16 gathers issued BACK-TO-BACK via volatile asm (enforced MLP=16).
    // The "memory" clobber prevents NVVM/ptxas from sinking the STS consumers
    // between the loads (the R3 failure mode that serialized the gathers).
    const float2* tb = reinterpret_cast<const float2*>(tables);
    float2 feat[NUM_LEVELS];
    #pragma unroll
    for (int l = 0; l < NUM_LEVELS; ++l) {
        const float2* ptr = tb + ((size_t)l << 19) + h[l];
        if (l < L1_CUTOFF)
            asm volatile("ld.global.nc.v2.f32 {%0,%1}, [%2];"
                         : "=f"(feat[l].x), "=f"(feat[l].y) : "l"(ptr) : "memory");
        else
            asm volatile("ld.global.cg.v2.f32 {%0,%1}, [%2];"
                         : "=f"(feat[l].x), "=f"(feat[l].y) : "l"(ptr) : "memory");
    }

    // Stage this thread's 128B row into smem.
    float2* row = reinterpret_cast<float2*>(sm + t * ROW_PAD);
    #pragma unroll
    for (int l = 0; l < NUM_LEVELS; ++l) row[l] = feat[l];

    // Phase 3: warp-local transpose copy-out. Warp owns 32 consecutive rows
    // = 4KB contiguous GMEM -> fully coalesced stores (32 wf/warp vs 256).
    __syncwarp();

    const int warp = t >> 5;
    const int lane = t & 31;
    float2* gout = reinterpret_cast<float2*>(out) +
                   ((size_t)(blockIdx.x * BLOCK + warp * 32)) * 16;
    const float* smw = sm + warp * 32 * ROW_PAD;

    #pragma unroll
    for (int i = 0; i < 16; ++i) {
        const int f2 = i * 32 + lane;         // float2 index within 32x16 chunk
        const int r  = f2 >> 4;               // source row within warp's tile
        const int c2 = f2 & 15;               // float2 col
        const float2 v = *reinterpret_cast<const float2*>(smw + r * ROW_PAD + c2 * 2);
        __stcs(gout + f2, v);                 // 256B contiguous per instruction
    }
}

extern "C" void kernel_launch(void* const* d_in, const int* in_sizes, int n_in,
                              void* d_out, int out_size)
{
    (void)in_sizes; (void)n_in; (void)out_size;

    // numpy-identical resolution computation (double precision, same op order)
    ResParams rp;
    const double l128 = log(128.0);
    for (int i = 0; i < NUM_LEVELS; ++i) {
        const int res = (int)floor(16.0 * exp(((double)i * l128) / 15.0));
        rp.rm1[i] = (float)(res - 1);
    }

    const float* pts    = (const float*)d_in[0];
    const float* tables = (const float*)d_in[1];
    float*       out    = (float*)d_out;

    hashenc_kernel<<<N_POINTS / BLOCK, BLOCK>>>(pts, tables, out, rp);
}

// round 5
// speedup vs baseline: 1.8138x; 1.8138x over previous
#include <cuda_runtime.h>
#include <math.h>

#define N_POINTS   4194304
#define NUM_LEVELS 16
#define HASH_MASK  ((1u << 19) - 1u)
#define BLOCK      256          // 8 warps = 16 points per block
#define PTS_PER_BLOCK (BLOCK / NUM_LEVELS)

// Per-level (res-1), host-computed with numpy-identical double math, passed by
// value (lives in the constant bank; baked into the graph at capture).
struct ResParams { float rm1[NUM_LEVELS]; };

// Layout: lane = (point & 1)*16 + level. One (point, level) pair per thread.
// -> gathers: 1 random 8B LDG per thread (1 wavefront per point-level, same as
//    the thread-per-point version — irreducible for hashed lookups)
// -> stores: consecutive lanes hit consecutive float2 of the output rows:
//    ONE coalesced 256B STG.64 per warp instead of 256 scattered wavefronts.
__global__ __launch_bounds__(BLOCK)
void hashenc_kernel(const float*  __restrict__ pts,
                    const float*  __restrict__ tables,
                    float*        __restrict__ out,
                    ResParams rp)
{
    const int t     = threadIdx.x;
    const int lane  = t & 31;
    const int level = lane & 15;
    const int sub   = lane >> 4;                     // which of the warp's 2 points
    const int warpg = (blockIdx.x * (BLOCK >> 5)) + (t >> 5);
    const size_t p  = (size_t)warpg * 2 + sub;       // point index

    // Each lane loads its point's coords. Warp touches only 2 points (24B):
    // ~1 wavefront per LDG via L1 broadcast. Streaming hint (single use).
    const float x = __ldcs(pts + 3 * p + 0);
    const float y = __ldcs(pts + 3 * p + 1);
    const float z = __ldcs(pts + 3 * p + 2);

    // normalize [-1,1] -> [0,1], clamp (matches jnp.clip((p+1)*0.5, 0, 1))
    const float fx = fminf(fmaxf((x + 1.0f) * 0.5f, 0.0f), 1.0f);
    const float fy = fminf(fmaxf((y + 1.0f) * 0.5f, 0.0f), 1.0f);
    const float fz = fminf(fmaxf((z + 1.0f) * 0.5f, 0.0f), 1.0f);

    // grid coords + hash for this lane's level
    const float rm1 = rp.rm1[level];                 // LDC, once per thread
    const unsigned cx = (unsigned)(fx * rm1);        // trunc == floor (non-neg)
    const unsigned cy = (unsigned)(fy * rm1);
    const unsigned cz = (unsigned)(fz * rm1);
    const unsigned h = (cx ^ (cy * 2654435761u) ^ (cz * 805459861u)) & HASH_MASK;

    // single gather (default caching keeps tables L2-resident)
    const float2 f = __ldg(reinterpret_cast<const float2*>(tables)
                           + ((size_t)level << 19) + h);

    // out[p][2*level .. 2*level+1]  ->  float2 index p*16 + level
    // = warpg*32 + sub*16 + level = warpg*32 + lane  -> fully coalesced.
    __stcs(reinterpret_cast<float2*>(out) + (size_t)warpg * 32 + lane, f);
}

extern "C" void kernel_launch(void* const* d_in, const int* in_sizes, int n_in,
                              void* d_out, int out_size)
{
    (void)in_sizes; (void)n_in; (void)out_size;

    // numpy-identical resolution computation (double precision, same op order)
    ResParams rp;
    const double l128 = log(128.0);
    for (int i = 0; i < NUM_LEVELS; ++i) {
        const int res = (int)floor(16.0 * exp(((double)i * l128) / 15.0));
        rp.rm1[i] = (float)(res - 1);
    }

    const float* pts    = (const float*)d_in[0];
    const float* tables = (const float*)d_in[1];
    float*       out    = (float*)d_out;

    // one thread per (point, level): N_POINTS * 16 threads
    const long long total = (long long)N_POINTS * NUM_LEVELS;
    hashenc_kernel<<<(unsigned)(total / BLOCK), BLOCK>>>(pts, tables, out, rp);
}

// round 6
// speedup vs baseline: 2.1683x; 1.1954x over previous
#include <cuda_runtime.h>
#include <math.h>

#define N_POINTS   4194304
#define NUM_LEVELS 16
#define HASH_MASK  ((1u << 19) - 1u)
#define BLOCK      256

// Per-level (res-1), host-computed with numpy-identical double math, passed by
// value (constant bank; baked into the captured graph).
struct ResParams { float rm1[NUM_LEVELS]; };

// Layout: each thread owns ONE point and TWO adjacent levels (2l, 2l+1).
//   lane = sub*8 + lpair,  sub = point-within-warp (0..3), lpair = 0..7
// -> gathers: 2 independent random 8B LDGs per thread (wavefront count per
//    point unchanged at 16 — irreducible for hashed lookups)
// -> store: the thread's two float2 results are CONTIGUOUS -> one STG.128;
//    across the warp: 32 x 16B = 512B contiguous, fully coalesced.
// -> normalize/clamp computed once per 8 lanes (was 16): half the ALU/gather.
__global__ __launch_bounds__(BLOCK)
void hashenc_kernel(const float*  __restrict__ pts,
                    const float*  __restrict__ tables,
                    float*        __restrict__ out,
                    ResParams rp)
{
    const int t     = threadIdx.x;
    const int lane  = t & 31;
    const int lpair = lane & 7;                 // level pair index
    const int sub   = lane >> 3;                // which of the warp's 4 points
    const int warpg = blockIdx.x * (BLOCK >> 5) + (t >> 5);
    const size_t p  = (size_t)warpg * 4 + sub;  // point index

    // 8 lanes share a point: loads broadcast within L1 (warp touches 48B).
    const float x = __ldcs(pts + 3 * p + 0);
    const float y = __ldcs(pts + 3 * p + 1);
    const float z = __ldcs(pts + 3 * p + 2);

    // normalize [-1,1] -> [0,1], clamp (matches jnp.clip((p+1)*0.5, 0, 1))
    const float fx = fminf(fmaxf((x + 1.0f) * 0.5f, 0.0f), 1.0f);
    const float fy = fminf(fmaxf((y + 1.0f) * 0.5f, 0.0f), 1.0f);
    const float fz = fminf(fmaxf((z + 1.0f) * 0.5f, 0.0f), 1.0f);

    const int l0 = lpair * 2;
    const int l1 = l0 + 1;

    // hashes for the two levels (trunc == floor for non-negative values)
    const float r0 = rp.rm1[l0];
    const unsigned h0 = (((unsigned)(fx * r0))
                      ^  ((unsigned)(fy * r0) * 2654435761u)
                      ^  ((unsigned)(fz * r0) * 805459861u)) & HASH_MASK;
    const float r1 = rp.rm1[l1];
    const unsigned h1 = (((unsigned)(fx * r1))
                      ^  ((unsigned)(fy * r1) * 2654435761u)
                      ^  ((unsigned)(fz * r1) * 805459861u)) & HASH_MASK;

    // two independent gathers (MLP=2/thread). Coarse levels (0-5) keep L1;
    // fine levels bypass L1 (.cg) so they don't thrash the coarse entries.
    const float2* tb = reinterpret_cast<const float2*>(tables);
    float2 f0, f1;
    if (lpair < 3) {
        f0 = __ldg (tb + ((size_t)l0 << 19) + h0);
        f1 = __ldg (tb + ((size_t)l1 << 19) + h1);
    } else {
        f0 = __ldcg(tb + ((size_t)l0 << 19) + h0);
        f1 = __ldcg(tb + ((size_t)l1 << 19) + h1);
    }

    // out float4 index = p*8 + lpair  -> warp writes 512B contiguous.
    const float4 v = make_float4(f0.x, f0.y, f1.x, f1.y);
    __stcs(reinterpret_cast<float4*>(out) + p * 8 + lpair, v);
}

extern "C" void kernel_launch(void* const* d_in, const int* in_sizes, int n_in,
                              void* d_out, int out_size)
{
    (void)in_sizes; (void)n_in; (void)out_size;

    // numpy-identical resolution computation (double precision, same op order)
    ResParams rp;
    const double l128 = log(128.0);
    for (int i = 0; i < NUM_LEVELS; ++i) {
        const int res = (int)floor(16.0 * exp(((double)i * l128) / 15.0));
        rp.rm1[i] = (float)(res - 1);
    }

    const float* pts    = (const float*)d_in[0];
    const float* tables = (const float*)d_in[1];
    float*       out    = (float*)d_out;

    // one thread per (point, level-pair): N_POINTS * 8 threads
    const long long total = (long long)N_POINTS * (NUM_LEVELS / 2);
    hashenc_kernel<<<(unsigned)(total / BLOCK), BLOCK>>>(pts, tables, out, rp);
}